// round 15
// baseline (speedup 1.0000x reference)
#include <cuda_runtime.h>
#include <cuda_fp16.h>
#include <cstdint>

#define N_NODES 50000
#define N_EDGES 600000
#define NFEAT 128
#define NGRAPH 64
#define POOL_ROWS 256
#define SCAN_ITEMS 49

#define GEMM_SMEM 24576  // A 16K | W 8K

// ---------------- device scratch ----------------
__device__ int g_deg[N_NODES];               // zero-init; re-zeroed by k_scan
__device__ int g_off[N_NODES + 1];
__device__ int g_pos[N_NODES];
__device__ int g_src[N_EDGES];
__device__ unsigned g_pool[NGRAPH * NFEAT];  // zero-init; re-zeroed by k_fc
// fp16 buffers: [node][128] half = 256B/row (64 uint words)
__device__ unsigned g_h16a[(size_t)N_NODES * 64];
__device__ unsigned g_h16b[(size_t)N_NODES * 64];
__device__ unsigned g_m16[(size_t)N_NODES * 64];   // mean operand
__device__ unsigned g_x16[(size_t)N_NODES * 64];   // layer-1 x operand
// W (fp16): [3 layers][128 n][256 k] half = 512B/row
__device__ uint4 g_Wh4[3 * 128 * 256 / 8];

// ---------------- helpers ----------------
__device__ __forceinline__ float lrelu(float v) { return fmaxf(v, 0.01f * v); }
__device__ __forceinline__ unsigned fenc(float f) {
    unsigned u = __float_as_uint(f);
    return (u & 0x80000000u) ? ~u : (u | 0x80000000u);
}
__device__ __forceinline__ float fdec(unsigned u) {
    return (u & 0x80000000u) ? __uint_as_float(u & 0x7FFFFFFFu) : __uint_as_float(~u);
}
__device__ __forceinline__ unsigned packh2(float a, float b) {
    __half2 p = __floats2half2_rn(a, b);
    return *reinterpret_cast<unsigned*>(&p);
}
__device__ __forceinline__ float2 h2f(unsigned u) {
    return __half22float2(*reinterpret_cast<const __half2*>(&u));
}
__device__ __forceinline__ uint32_t smem_u32(const void* p) {
    uint32_t a;
    asm("{ .reg .u64 t; cvta.to.shared.u64 t, %1; cvt.u32.u64 %0, t; }" : "=r"(a) : "l"(p));
    return a;
}
__device__ __forceinline__ void mma_f16(float* c, const uint32_t* a, uint32_t b0,
                                        uint32_t b1) {
    asm volatile(
        "mma.sync.aligned.m16n8k16.row.col.f32.f16.f16.f32 "
        "{%0,%1,%2,%3}, {%4,%5,%6,%7}, {%8,%9}, {%0,%1,%2,%3};"
        : "+f"(c[0]), "+f"(c[1]), "+f"(c[2]), "+f"(c[3])
        : "r"(a[0]), "r"(a[1]), "r"(a[2]), "r"(a[3]), "r"(b0), "r"(b1));
}
__device__ __forceinline__ void ldsm4(uint32_t* r, uint32_t addr) {
    asm volatile("ldmatrix.sync.aligned.m8n8.x4.shared.b16 {%0,%1,%2,%3}, [%4];"
                 : "=r"(r[0]), "=r"(r[1]), "=r"(r[2]), "=r"(r[3]) : "r"(addr));
}
__device__ __forceinline__ void cp16(uint32_t dst, const void* src, int sz) {
    asm volatile("cp.async.ca.shared.global [%0], [%1], 16, %2;"
                 :: "r"(dst), "l"(src), "r"(sz));
}

// ---------------- fused: W pre-convert (fp16) + degree histogram ----------------
__global__ void k_whist(const float* __restrict__ W1l, const float* __restrict__ W1r,
                        const float* __restrict__ W2l, const float* __restrict__ W2r,
                        const float* __restrict__ W3l, const float* __restrict__ W3r,
                        const int* __restrict__ ei) {
    int i = blockIdx.x * blockDim.x + threadIdx.x;
    if (i < 3 * 128 * 256) {
        int l = i >> 15;
        int rem = i & 32767;
        int n = rem >> 8;
        int k = rem & 255;
        const float* Wl = (l == 0) ? W1l : (l == 1) ? W2l : W3l;
        const float* Wr = (l == 0) ? W1r : (l == 1) ? W2r : W3r;
        float w = (k < 128) ? Wl[k * 128 + n] : Wr[(k - 128) * 128 + n];
        ((__half*)g_Wh4)[i] = __float2half_rn(w);
    }
    int e4 = i * 4;
    if (e4 < N_EDGES) {
        int4 d = *(const int4*)(ei + N_EDGES + e4);
        atomicAdd(&g_deg[d.x], 1);
        atomicAdd(&g_deg[d.y], 1);
        atomicAdd(&g_deg[d.z], 1);
        atomicAdd(&g_deg[d.w], 1);
    }
}

// single-block scan; consumes g_deg and re-zeroes it for the next replay
__global__ void k_scan() {
    __shared__ int s[1024];
    int t = threadIdx.x;
    int base = t * SCAN_ITEMS;
    int sum = 0;
    for (int j = 0; j < SCAN_ITEMS; j++) {
        int i = base + j;
        if (i < N_NODES) sum += g_deg[i];
    }
    s[t] = sum;
    for (int off = 1; off < 1024; off <<= 1) {
        __syncthreads();
        int v = (t >= off) ? s[t - off] : 0;
        __syncthreads();
        s[t] += v;
    }
    __syncthreads();
    int run = s[t] - sum;
    for (int j = 0; j < SCAN_ITEMS; j++) {
        int i = base + j;
        if (i < N_NODES) {
            int d = g_deg[i];
            g_off[i] = run;
            g_pos[i] = run;
            run += d;
            g_deg[i] = 0;
        }
    }
    if (t == 1023) g_off[N_NODES] = N_EDGES;
}

__global__ void k_scatter(const int* __restrict__ ei) {
    int e4 = (blockIdx.x * blockDim.x + threadIdx.x) * 4;
    if (e4 >= N_EDGES) return;
    int4 d = *(const int4*)(ei + N_EDGES + e4);
    int4 s = *(const int4*)(ei + e4);
    int p0 = atomicAdd(&g_pos[d.x], 1);
    int p1 = atomicAdd(&g_pos[d.y], 1);
    int p2 = atomicAdd(&g_pos[d.z], 1);
    int p3 = atomicAdd(&g_pos[d.w], 1);
    g_src[p0] = s.x;
    g_src[p1] = s.y;
    g_src[p2] = s.z;
    g_src[p3] = s.w;
}

// ---------------- mean-aggregation, fp32 input (layer 1), 8-way MLP ----------------
__global__ __launch_bounds__(256) void k_agg32(const float* __restrict__ in,
                                               uint2* __restrict__ m16,
                                               uint2* __restrict__ x16) {
    int node = (blockIdx.x * blockDim.x + threadIdx.x) >> 5;
    if (node >= N_NODES) return;
    int lane = threadIdx.x & 31;
    float4 sv = ((const float4*)(in + (size_t)node * NFEAT))[lane];
    x16[node * 32 + lane] = make_uint2(packh2(sv.x, sv.y), packh2(sv.z, sv.w));
    int s0 = g_off[node], s1 = g_off[node + 1];
    float ax = 0.f, ay = 0.f, az = 0.f, aw = 0.f;
    int e = s0;
    for (; e + 7 < s1; e += 8) {
        float4 v[8];
#pragma unroll
        for (int j = 0; j < 8; j++)
            v[j] = ((const float4*)(in + (size_t)g_src[e + j] * NFEAT))[lane];
#pragma unroll
        for (int j = 0; j < 8; j++) {
            ax += v[j].x; ay += v[j].y; az += v[j].z; aw += v[j].w;
        }
    }
    for (; e < s1; ++e) {
        float4 v = ((const float4*)(in + (size_t)g_src[e] * NFEAT))[lane];
        ax += v.x; ay += v.y; az += v.z; aw += v.w;
    }
    float inv = 1.0f / (float)max(s1 - s0, 1);
    m16[node * 32 + lane] =
        make_uint2(packh2(ax * inv, ay * inv), packh2(az * inv, aw * inv));
}

// ---------------- mean-aggregation, fp16 input (layers 2,3), 8-way MLP -------------
__global__ __launch_bounds__(256) void k_agg16(const unsigned* __restrict__ in16,
                                               uint2* __restrict__ m16) {
    int node = (blockIdx.x * blockDim.x + threadIdx.x) >> 5;
    if (node >= N_NODES) return;
    int lane = threadIdx.x & 31;
    int s0 = g_off[node], s1 = g_off[node + 1];
    float ax = 0.f, ay = 0.f, az = 0.f, aw = 0.f;
    int e = s0;
    for (; e + 7 < s1; e += 8) {
        uint2 u[8];
#pragma unroll
        for (int j = 0; j < 8; j++)
            u[j] = ((const uint2*)in16)[g_src[e + j] * 32 + lane];
#pragma unroll
        for (int j = 0; j < 8; j++) {
            float2 a = h2f(u[j].x), b = h2f(u[j].y);
            ax += a.x; ay += a.y; az += b.x; aw += b.y;
        }
    }
    for (; e < s1; ++e) {
        uint2 u = ((const uint2*)in16)[g_src[e] * 32 + lane];
        float2 a = h2f(u.x), b = h2f(u.y);
        ax += a.x; ay += a.y; az += b.x; aw += b.y;
    }
    float inv = 1.0f / (float)max(s1 - s0, 1);
    m16[node * 32 + lane] =
        make_uint2(packh2(ax * inv, ay * inv), packh2(az * inv, aw * inv));
}

// ---------------- mma.sync dual GEMM, BM=128 x BN=64, 4 CTA/SM ----------------------
// Grid: (391 m-blocks) x (2 n-blocks) flattened; bx>>1 = m, bx&1 = n-block.
// 4 k-chunks of 64; 8 warps = 4m x 2n (warp 32m x 32n). Stage (24KB): A@0 16K, W@16K 8K.
__global__ __launch_bounds__(256, 4) void k_gemm(
    const unsigned* __restrict__ Am, const unsigned* __restrict__ Ax,
    const uint4* __restrict__ Bh,
    const float* __restrict__ bias, unsigned* __restrict__ out16) {
    extern __shared__ char smc[];
    uint32_t sb = smem_u32(smc);
    int t = threadIdx.x, lane = t & 31, wid = t >> 5;
    int qr = lane >> 2, qc = lane & 3;
    int row0 = (blockIdx.x >> 1) * 128;
    int nblk = blockIdx.x & 1;  // which 64-col half of W/out
    int wrow = (wid & 3) * 32, wcol = (wid >> 2) * 32;

    float acc[2][2][2][4];
#pragma unroll
    for (int a = 0; a < 2; a++)
#pragma unroll
        for (int b = 0; b < 2; b++)
#pragma unroll
            for (int c = 0; c < 2; c++)
#pragma unroll
                for (int d = 0; d < 4; d++) acc[a][b][c][d] = 0.f;

#define STAGE(CH)                                                                   \
    {                                                                               \
        const int _ch = (CH);                                                       \
        const char* asrc = (const char*)(_ch < 2 ? Am : Ax);                        \
        int kof = (_ch & 1) * 128, bkof = _ch * 128;                                \
        for (int g = t; g < 1536; g += 256) {                                       \
            if (g < 1024) {                                                         \
                int row = g >> 3, c16 = g & 7;                                      \
                uint32_t dst = sb + row * 128 + ((c16 ^ (row & 7)) * 16);           \
                int grow = row0 + row;                                              \
                cp16(dst, asrc + (size_t)grow * 256 + kof + c16 * 16,               \
                     grow < N_NODES ? 16 : 0);                                      \
            } else {                                                                \
                int idx = g - 1024, row = idx >> 3, c16 = idx & 7;                  \
                uint32_t dst = sb + 16384 + row * 128 + ((c16 ^ (row & 7)) * 16);   \
                cp16(dst, (const char*)Bh + (nblk * 64 + row) * 512 + bkof +        \
                              c16 * 16, 16);                                        \
            }                                                                       \
        }                                                                           \
        asm volatile("cp.async.commit_group;");                                     \
    }

    for (int ch = 0; ch < 4; ch++) {
        STAGE(ch);
        asm volatile("cp.async.wait_group 0;");
        __syncthreads();
#pragma unroll
        for (int ks = 0; ks < 4; ks++) {
            uint32_t ah[2][4];
#pragma unroll
            for (int mi = 0; mi < 2; mi++) {
                int row = wrow + mi * 16 + (lane & 15);
                int c16 = ks * 2 + (lane >> 4);
                ldsm4(ah[mi], sb + row * 128 + ((c16 ^ (row & 7)) * 16));
            }
#pragma unroll
            for (int ni2 = 0; ni2 < 2; ni2++) {
                int row = wcol + ni2 * 16 + (lane & 7) + ((lane >> 4) << 3);
                int c16 = ks * 2 + ((lane >> 3) & 1);
                uint32_t bh[4];
                ldsm4(bh, sb + 16384 + row * 128 + ((c16 ^ (row & 7)) * 16));
#pragma unroll
                for (int mi = 0; mi < 2; mi++) {
                    mma_f16(acc[mi][ni2][0], ah[mi], bh[0], bh[1]);
                    mma_f16(acc[mi][ni2][1], ah[mi], bh[2], bh[3]);
                }
            }
        }
        __syncthreads();
    }
#undef STAGE

    // epilogue: bias + leaky_relu, fp16 half2 stores
#pragma unroll
    for (int ni2 = 0; ni2 < 2; ni2++)
#pragma unroll
        for (int n8 = 0; n8 < 2; n8++) {
            int col = nblk * 64 + wcol + ni2 * 16 + n8 * 8 + qc * 2;
            float b0 = __ldg(bias + col), b1 = __ldg(bias + col + 1);
#pragma unroll
            for (int mi = 0; mi < 2; mi++) {
                float* a = acc[mi][ni2][n8];
                int r = row0 + wrow + mi * 16 + qr;
                if (r < N_NODES)
                    out16[(size_t)r * 64 + (col >> 1)] =
                        packh2(lrelu(a[0] + b0), lrelu(a[1] + b1));
                if (r + 8 < N_NODES)
                    out16[(size_t)(r + 8) * 64 + (col >> 1)] =
                        packh2(lrelu(a[2] + b0), lrelu(a[3] + b1));
            }
        }
}

// ---------------- global max pool (fp16 input) ----------------
__global__ void k_pool(const unsigned* __restrict__ h16, const int* __restrict__ batch) {
    int t = threadIdx.x;  // column 0..127
    const __half* h = (const __half*)h16;
    int r0 = blockIdx.x * POOL_ROWS;
    int r1 = min(r0 + POOL_ROWS, N_NODES);
    if (r0 >= N_NODES) return;
    int curg = batch[r0];
    float m = -3.402823466e38f;
    for (int r = r0; r < r1; ++r) {
        int g = batch[r];
        if (g != curg) {
            atomicMax(&g_pool[curg * NFEAT + t], fenc(m));
            curg = g;
            m = -3.402823466e38f;
        }
        m = fmaxf(m, __half2float(h[(size_t)r * NFEAT + t]));
    }
    atomicMax(&g_pool[curg * NFEAT + t], fenc(m));
}

// ---------------- final FC; re-zeroes g_pool for the next replay ----------------
__global__ void k_fc(const float* __restrict__ Wfc, const float* __restrict__ bfc,
                     float* __restrict__ out) {
    int t = threadIdx.x;
    int g = t >> 1, o = t & 1;
    float s = bfc[o];
#pragma unroll 4
    for (int k = 0; k < 128; k++) s += fdec(g_pool[g * NFEAT + k]) * Wfc[k * 2 + o];
    out[g * 2 + o] = s;
    __syncthreads();
    for (int k = t; k < NGRAPH * NFEAT; k += 128) g_pool[k] = 0u;
}

// ---------------- launch ----------------
extern "C" void kernel_launch(void* const* d_in, const int* in_sizes, int n_in,
                              void* d_out, int out_size) {
    const float* x = (const float*)d_in[0];
    const int* ei = (const int*)d_in[1];
    const int* batch = (const int*)d_in[2];
    const float* b1 = (const float*)d_in[4];
    const float* b2 = (const float*)d_in[7];
    const float* b3 = (const float*)d_in[10];
    const float* Wfc = (const float*)d_in[12];
    const float* bfc = (const float*)d_in[13];
    float* out = (float*)d_out;

    unsigned *h16a, *h16b, *m16, *x16;
    uint4* wh;
    cudaGetSymbolAddress((void**)&h16a, g_h16a);
    cudaGetSymbolAddress((void**)&h16b, g_h16b);
    cudaGetSymbolAddress((void**)&m16, g_m16);
    cudaGetSymbolAddress((void**)&x16, g_x16);
    cudaGetSymbolAddress((void**)&wh, g_Wh4);

    cudaFuncSetAttribute(k_gemm, cudaFuncAttributeMaxDynamicSharedMemorySize, GEMM_SMEM);

    const int gemm_blocks = ((N_NODES + 127) / 128) * 2;   // 391 m x 2 n = 782
    const int agg_blocks = (N_NODES * 32 + 255) / 256;
    const int edge4_blocks = (N_EDGES / 4 + 255) / 256;    // 586
    const int LSTRIDE = 128 * 256 / 8;  // uint4 per layer

    k_whist<<<edge4_blocks, 256>>>(
        (const float*)d_in[3], (const float*)d_in[5], (const float*)d_in[6],
        (const float*)d_in[8], (const float*)d_in[9], (const float*)d_in[11], ei);
    k_scan<<<1, 1024>>>();
    k_scatter<<<edge4_blocks, 256>>>(ei);

    // layer 1 (agg32 = idx 3 -> profiled slot)
    k_agg32<<<agg_blocks, 256>>>(x, (uint2*)m16, (uint2*)x16);
    k_gemm<<<gemm_blocks, 256, GEMM_SMEM>>>(m16, x16, wh, b1, h16a);
    // layer 2 (x-operand = h16a directly)
    k_agg16<<<agg_blocks, 256>>>(h16a, (uint2*)m16);
    k_gemm<<<gemm_blocks, 256, GEMM_SMEM>>>(m16, h16a, wh + LSTRIDE, b2, h16b);
    // layer 3
    k_agg16<<<agg_blocks, 256>>>(h16b, (uint2*)m16);
    k_gemm<<<gemm_blocks, 256, GEMM_SMEM>>>(m16, h16b, wh + 2 * LSTRIDE, b3, h16a);

    // pool + fc (fc re-zeroes g_pool)
    k_pool<<<(N_NODES + POOL_ROWS - 1) / POOL_ROWS, 128>>>(h16a, batch);
    k_fc<<<1, 128>>>(Wfc, bfc, out);
}

// round 17
// speedup vs baseline: 1.0026x; 1.0026x over previous
#include <cuda_runtime.h>
#include <cuda_fp16.h>
#include <cstdint>

#define N_NODES 50000
#define N_EDGES 600000
#define NFEAT 128
#define NGRAPH 64
#define POOL_ROWS 256
#define SCAN_ITEMS 49

#define GEMM_SMEM 32768  // A 16K | W 16K

// ---------------- device scratch ----------------
__device__ int g_deg[N_NODES];               // zero-init; re-zeroed by k_scan
__device__ int g_off[N_NODES + 1];
__device__ int g_pos[N_NODES];
__device__ int g_src[N_EDGES];
__device__ unsigned g_pool[NGRAPH * NFEAT];  // zero-init; re-zeroed by k_fc
// fp16 buffers: [node][128] half = 256B/row (64 uint words)
__device__ unsigned g_h16a[(size_t)N_NODES * 64];
__device__ unsigned g_h16b[(size_t)N_NODES * 64];
__device__ unsigned g_m16[(size_t)N_NODES * 64];   // mean operand
__device__ unsigned g_x16[(size_t)N_NODES * 64];   // layer-1 x operand (fp16 of x)
// W (fp16): [3 layers][128 n][256 k] half = 512B/row
__device__ uint4 g_Wh4[3 * 128 * 256 / 8];

// ---------------- helpers ----------------
__device__ __forceinline__ float lrelu(float v) { return fmaxf(v, 0.01f * v); }
__device__ __forceinline__ unsigned fenc(float f) {
    unsigned u = __float_as_uint(f);
    return (u & 0x80000000u) ? ~u : (u | 0x80000000u);
}
__device__ __forceinline__ float fdec(unsigned u) {
    return (u & 0x80000000u) ? __uint_as_float(u & 0x7FFFFFFFu) : __uint_as_float(~u);
}
__device__ __forceinline__ unsigned packh2(float a, float b) {
    __half2 p = __floats2half2_rn(a, b);
    return *reinterpret_cast<unsigned*>(&p);
}
__device__ __forceinline__ float2 h2f(unsigned u) {
    return __half22float2(*reinterpret_cast<const __half2*>(&u));
}
__device__ __forceinline__ uint32_t smem_u32(const void* p) {
    uint32_t a;
    asm("{ .reg .u64 t; cvta.to.shared.u64 t, %1; cvt.u32.u64 %0, t; }" : "=r"(a) : "l"(p));
    return a;
}
__device__ __forceinline__ void mma_f16(float* c, const uint32_t* a, uint32_t b0,
                                        uint32_t b1) {
    asm volatile(
        "mma.sync.aligned.m16n8k16.row.col.f32.f16.f16.f32 "
        "{%0,%1,%2,%3}, {%4,%5,%6,%7}, {%8,%9}, {%0,%1,%2,%3};"
        : "+f"(c[0]), "+f"(c[1]), "+f"(c[2]), "+f"(c[3])
        : "r"(a[0]), "r"(a[1]), "r"(a[2]), "r"(a[3]), "r"(b0), "r"(b1));
}
__device__ __forceinline__ void ldsm4(uint32_t* r, uint32_t addr) {
    asm volatile("ldmatrix.sync.aligned.m8n8.x4.shared.b16 {%0,%1,%2,%3}, [%4];"
                 : "=r"(r[0]), "=r"(r[1]), "=r"(r[2]), "=r"(r[3]) : "r"(addr));
}
__device__ __forceinline__ void cp16(uint32_t dst, const void* src, int sz) {
    asm volatile("cp.async.ca.shared.global [%0], [%1], 16, %2;"
                 :: "r"(dst), "l"(src), "r"(sz));
}

// ---------------- fused: W->fp16 + x->fp16 + degree histogram (8-way) --------------
__global__ void k_whist(const float* __restrict__ W1l, const float* __restrict__ W1r,
                        const float* __restrict__ W2l, const float* __restrict__ W2r,
                        const float* __restrict__ W3l, const float* __restrict__ W3r,
                        const float* __restrict__ x, uint2* __restrict__ x16,
                        const int* __restrict__ ei) {
    int i = blockIdx.x * blockDim.x + threadIdx.x;
    int nthr = gridDim.x * blockDim.x;
    if (i < 3 * 128 * 256) {
        int l = i >> 15;
        int rem = i & 32767;
        int n = rem >> 8;
        int k = rem & 255;
        const float* Wl = (l == 0) ? W1l : (l == 1) ? W2l : W3l;
        const float* Wr = (l == 0) ? W1r : (l == 1) ? W2r : W3r;
        float w = (k < 128) ? Wl[k * 128 + n] : Wr[(k - 128) * 128 + n];
        ((__half*)g_Wh4)[i] = __float2half_rn(w);
    }
    // x -> fp16 (grid-stride over 1.6M uint2 = 4 floats each)
    for (int j = i; j < N_NODES * 32; j += nthr) {
        float4 v = ((const float4*)x)[j];
        x16[j] = make_uint2(packh2(v.x, v.y), packh2(v.z, v.w));
    }
    // degree histogram, 8 edges/thread
    int e8 = i * 8;
    if (e8 < N_EDGES) {
        int4 d0 = *(const int4*)(ei + N_EDGES + e8);
        int4 d1 = *(const int4*)(ei + N_EDGES + e8 + 4);
        atomicAdd(&g_deg[d0.x], 1);
        atomicAdd(&g_deg[d0.y], 1);
        atomicAdd(&g_deg[d0.z], 1);
        atomicAdd(&g_deg[d0.w], 1);
        atomicAdd(&g_deg[d1.x], 1);
        atomicAdd(&g_deg[d1.y], 1);
        atomicAdd(&g_deg[d1.z], 1);
        atomicAdd(&g_deg[d1.w], 1);
    }
}

// single-block scan; consumes g_deg and re-zeroes it for the next replay
__global__ void k_scan() {
    __shared__ int s[1024];
    int t = threadIdx.x;
    int base = t * SCAN_ITEMS;
    int sum = 0;
    for (int j = 0; j < SCAN_ITEMS; j++) {
        int i = base + j;
        if (i < N_NODES) sum += g_deg[i];
    }
    s[t] = sum;
    for (int off = 1; off < 1024; off <<= 1) {
        __syncthreads();
        int v = (t >= off) ? s[t - off] : 0;
        __syncthreads();
        s[t] += v;
    }
    __syncthreads();
    int run = s[t] - sum;
    for (int j = 0; j < SCAN_ITEMS; j++) {
        int i = base + j;
        if (i < N_NODES) {
            int d = g_deg[i];
            g_off[i] = run;
            g_pos[i] = run;
            run += d;
            g_deg[i] = 0;
        }
    }
    if (t == 1023) g_off[N_NODES] = N_EDGES;
}

// scatter, 8 edges/thread
__global__ void k_scatter(const int* __restrict__ ei) {
    int e8 = (blockIdx.x * blockDim.x + threadIdx.x) * 8;
    if (e8 >= N_EDGES) return;
    int4 d0 = *(const int4*)(ei + N_EDGES + e8);
    int4 d1 = *(const int4*)(ei + N_EDGES + e8 + 4);
    int4 s0 = *(const int4*)(ei + e8);
    int4 s1 = *(const int4*)(ei + e8 + 4);
    int p0 = atomicAdd(&g_pos[d0.x], 1);
    int p1 = atomicAdd(&g_pos[d0.y], 1);
    int p2 = atomicAdd(&g_pos[d0.z], 1);
    int p3 = atomicAdd(&g_pos[d0.w], 1);
    int p4 = atomicAdd(&g_pos[d1.x], 1);
    int p5 = atomicAdd(&g_pos[d1.y], 1);
    int p6 = atomicAdd(&g_pos[d1.z], 1);
    int p7 = atomicAdd(&g_pos[d1.w], 1);
    g_src[p0] = s0.x;
    g_src[p1] = s0.y;
    g_src[p2] = s0.z;
    g_src[p3] = s0.w;
    g_src[p4] = s1.x;
    g_src[p5] = s1.y;
    g_src[p6] = s1.z;
    g_src[p7] = s1.w;
}

// ---------------- mean-aggregation, fp16 input (all layers), 8-way MLP -------------
__global__ __launch_bounds__(256) void k_agg16(const unsigned* __restrict__ in16,
                                               uint2* __restrict__ m16) {
    int node = (blockIdx.x * blockDim.x + threadIdx.x) >> 5;
    if (node >= N_NODES) return;
    int lane = threadIdx.x & 31;
    int s0 = g_off[node], s1 = g_off[node + 1];
    float ax = 0.f, ay = 0.f, az = 0.f, aw = 0.f;
    int e = s0;
    for (; e + 7 < s1; e += 8) {
        uint2 u[8];
#pragma unroll
        for (int j = 0; j < 8; j++)
            u[j] = ((const uint2*)in16)[g_src[e + j] * 32 + lane];
#pragma unroll
        for (int j = 0; j < 8; j++) {
            float2 a = h2f(u[j].x), b = h2f(u[j].y);
            ax += a.x; ay += a.y; az += b.x; aw += b.y;
        }
    }
    for (; e < s1; ++e) {
        uint2 u = ((const uint2*)in16)[g_src[e] * 32 + lane];
        float2 a = h2f(u.x), b = h2f(u.y);
        ax += a.x; ay += a.y; az += b.x; aw += b.y;
    }
    float inv = 1.0f / (float)max(s1 - s0, 1);
    m16[node * 32 + lane] =
        make_uint2(packh2(ax * inv, ay * inv), packh2(az * inv, aw * inv));
}

// ---------------- mma.sync dual GEMM (R14 config: BM=128, BN=128, 2 CTA/SM) --------
// Tile: 128m x 128n x 256k; 4 k-chunks of 64; 8 warps = 4m x 2n (warp 32m x 64n).
// smem stage (32KB): A@0 (16K), W@16K; [128 rows][64 half = 128B], swizzled.
__global__ __launch_bounds__(256, 2) void k_gemm(
    const unsigned* __restrict__ Am, const unsigned* __restrict__ Ax,
    const uint4* __restrict__ Bh,
    const float* __restrict__ bias, unsigned* __restrict__ out16) {
    extern __shared__ char smc[];
    uint32_t sb = smem_u32(smc);
    int t = threadIdx.x, lane = t & 31, wid = t >> 5;
    int qr = lane >> 2, qc = lane & 3;
    int row0 = blockIdx.x * 128;
    int wrow = (wid & 3) * 32, wcol = (wid >> 2) * 64;

    float acc[2][4][2][4];
#pragma unroll
    for (int a = 0; a < 2; a++)
#pragma unroll
        for (int b = 0; b < 4; b++)
#pragma unroll
            for (int c = 0; c < 2; c++)
#pragma unroll
                for (int d = 0; d < 4; d++) acc[a][b][c][d] = 0.f;

#define STAGE(CH)                                                                   \
    {                                                                               \
        const int _ch = (CH);                                                       \
        const char* asrc = (const char*)(_ch < 2 ? Am : Ax);                        \
        int kof = (_ch & 1) * 128, bkof = _ch * 128;                                \
        for (int g = t; g < 2048; g += 256) {                                       \
            int arr = g >> 10, idx = g & 1023, row = idx >> 3, c16 = idx & 7;       \
            uint32_t dst = sb + arr * 16384 + row * 128 + ((c16 ^ (row & 7)) * 16); \
            if (arr == 0) {                                                         \
                int grow = row0 + row;                                              \
                cp16(dst, asrc + (size_t)grow * 256 + kof + c16 * 16,               \
                     grow < N_NODES ? 16 : 0);                                      \
            } else {                                                                \
                cp16(dst, (const char*)Bh + row * 512 + bkof + c16 * 16, 16);       \
            }                                                                       \
        }                                                                           \
        asm volatile("cp.async.commit_group;");                                     \
    }

    for (int ch = 0; ch < 4; ch++) {
        STAGE(ch);
        asm volatile("cp.async.wait_group 0;");
        __syncthreads();
#pragma unroll
        for (int ks = 0; ks < 4; ks++) {
            uint32_t ah[2][4];
#pragma unroll
            for (int mi = 0; mi < 2; mi++) {
                int row = wrow + mi * 16 + (lane & 15);
                int c16 = ks * 2 + (lane >> 4);
                ldsm4(ah[mi], sb + row * 128 + ((c16 ^ (row & 7)) * 16));
            }
#pragma unroll
            for (int ni2 = 0; ni2 < 4; ni2++) {
                int row = wcol + ni2 * 16 + (lane & 7) + ((lane >> 4) << 3);
                int c16 = ks * 2 + ((lane >> 3) & 1);
                uint32_t bh[4];
                ldsm4(bh, sb + 16384 + row * 128 + ((c16 ^ (row & 7)) * 16));
#pragma unroll
                for (int mi = 0; mi < 2; mi++) {
                    mma_f16(acc[mi][ni2][0], ah[mi], bh[0], bh[1]);
                    mma_f16(acc[mi][ni2][1], ah[mi], bh[2], bh[3]);
                }
            }
        }
        __syncthreads();
    }
#undef STAGE

    // epilogue: bias + leaky_relu, fp16 half2 stores
#pragma unroll
    for (int ni2 = 0; ni2 < 4; ni2++)
#pragma unroll
        for (int n8 = 0; n8 < 2; n8++) {
            int col = wcol + ni2 * 16 + n8 * 8 + qc * 2;
            float b0 = __ldg(bias + col), b1 = __ldg(bias + col + 1);
#pragma unroll
            for (int mi = 0; mi < 2; mi++) {
                float* a = acc[mi][ni2][n8];
                int r = row0 + wrow + mi * 16 + qr;
                if (r < N_NODES)
                    out16[(size_t)r * 64 + (col >> 1)] =
                        packh2(lrelu(a[0] + b0), lrelu(a[1] + b1));
                if (r + 8 < N_NODES)
                    out16[(size_t)(r + 8) * 64 + (col >> 1)] =
                        packh2(lrelu(a[2] + b0), lrelu(a[3] + b1));
            }
        }
}

// ---------------- global max pool (fp16 input) ----------------
__global__ void k_pool(const unsigned* __restrict__ h16, const int* __restrict__ batch) {
    int t = threadIdx.x;  // column 0..127
    const __half* h = (const __half*)h16;
    int r0 = blockIdx.x * POOL_ROWS;
    int r1 = min(r0 + POOL_ROWS, N_NODES);
    if (r0 >= N_NODES) return;
    int curg = batch[r0];
    float m = -3.402823466e38f;
    for (int r = r0; r < r1; ++r) {
        int g = batch[r];
        if (g != curg) {
            atomicMax(&g_pool[curg * NFEAT + t], fenc(m));
            curg = g;
            m = -3.402823466e38f;
        }
        m = fmaxf(m, __half2float(h[(size_t)r * NFEAT + t]));
    }
    atomicMax(&g_pool[curg * NFEAT + t], fenc(m));
}

// ---------------- final FC; re-zeroes g_pool for the next replay ----------------
__global__ void k_fc(const float* __restrict__ Wfc, const float* __restrict__ bfc,
                     float* __restrict__ out) {
    int t = threadIdx.x;
    int g = t >> 1, o = t & 1;
    float s = bfc[o];
#pragma unroll 4
    for (int k = 0; k < 128; k++) s += fdec(g_pool[g * NFEAT + k]) * Wfc[k * 2 + o];
    out[g * 2 + o] = s;
    __syncthreads();
    for (int k = t; k < NGRAPH * NFEAT; k += 128) g_pool[k] = 0u;
}

// ---------------- launch ----------------
extern "C" void kernel_launch(void* const* d_in, const int* in_sizes, int n_in,
                              void* d_out, int out_size) {
    const float* x = (const float*)d_in[0];
    const int* ei = (const int*)d_in[1];
    const int* batch = (const int*)d_in[2];
    const float* b1 = (const float*)d_in[4];
    const float* b2 = (const float*)d_in[7];
    const float* b3 = (const float*)d_in[10];
    const float* Wfc = (const float*)d_in[12];
    const float* bfc = (const float*)d_in[13];
    float* out = (float*)d_out;

    unsigned *h16a, *h16b, *m16, *x16;
    uint4* wh;
    cudaGetSymbolAddress((void**)&h16a, g_h16a);
    cudaGetSymbolAddress((void**)&h16b, g_h16b);
    cudaGetSymbolAddress((void**)&m16, g_m16);
    cudaGetSymbolAddress((void**)&x16, g_x16);
    cudaGetSymbolAddress((void**)&wh, g_Wh4);

    cudaFuncSetAttribute(k_gemm, cudaFuncAttributeMaxDynamicSharedMemorySize, GEMM_SMEM);

    const int gemm_blocks = (N_NODES + 127) / 128;         // 391
    const int agg_blocks = (N_NODES * 32 + 255) / 256;
    const int whist_blocks = 586;                          // 150016 threads
    const int edge8_blocks = (N_EDGES / 8 + 255) / 256;    // 293
    const int LSTRIDE = 128 * 256 / 8;  // uint4 per layer

    k_whist<<<whist_blocks, 256>>>(
        (const float*)d_in[3], (const float*)d_in[5], (const float*)d_in[6],
        (const float*)d_in[8], (const float*)d_in[9], (const float*)d_in[11], x,
        (uint2*)x16, ei);
    k_scan<<<1, 1024>>>();
    k_scatter<<<edge8_blocks, 256>>>(ei);

    // layer 1 (agg16 = idx 3 -> profiled slot; x-operand = pre-converted x16)
    k_agg16<<<agg_blocks, 256>>>(x16, (uint2*)m16);
    k_gemm<<<gemm_blocks, 256, GEMM_SMEM>>>(m16, x16, wh, b1, h16a);
    // layer 2 (x-operand = h16a directly)
    k_agg16<<<agg_blocks, 256>>>(h16a, (uint2*)m16);
    k_gemm<<<gemm_blocks, 256, GEMM_SMEM>>>(m16, h16a, wh + LSTRIDE, b2, h16b);
    // layer 3
    k_agg16<<<agg_blocks, 256>>>(h16b, (uint2*)m16);
    k_gemm<<<gemm_blocks, 256, GEMM_SMEM>>>(m16, h16b, wh + 2 * LSTRIDE, b3, h16a);

    // pool + fc (fc re-zeroes g_pool)
    k_pool<<<(N_NODES + POOL_ROWS - 1) / POOL_ROWS, 128>>>(h16a, batch);
    k_fc<<<1, 128>>>(Wfc, bfc, out);
}